// round 7
// baseline (speedup 1.0000x reference)
#include <cuda_runtime.h>
#include <cuda_fp16.h>
#include <cstdint>

// Conv2D 3x3 s1 p1: x[8,16,512,512] fp32 * w[16,144] -> out[8,16,512,512]
// Implicit GEMM on mma.sync.m16n8k16 (f16, f32 acc), persistent CTAs, depth-1
// cp.async pipeline (16B interior + 4B halo), ldmatrix A-frags, half2 cvt.
// R7: smem-transposed epilogue -> coalesced STG.128 (ns buffer reused as fp32
// staging, 2 rounds of 8 c_out). CTA tile: 32(x) x 16(y), all 16 co, 8 warps.

#define HW     512
#define NSX    34
#define NSY    18
#define CPAD   24        // ci stride (halves): 48B rows, LDSM conflict-free
#define RAWROW 36        // raw row: [0..31]=interior, [32]=x0-1, [33]=x0+32
#define NTILES 4096
#define GRID   456       // 3 CTAs/SM x 152 SMs
#define TCO    516       // transpose co-stride (floats), == 4 mod 32

#define RAW_OFF 0                          // 16*18*36*4 = 41472 B
#define NS_OFF  41472                      // 18*34*24*2 = 29376 B (>= 8*516*4=16512 for T)
#define BS_OFF  (41472 + 29376)            // 70848
#define SM_TOTAL (70848 + 4608)            // 75456 B -> 3 CTAs/SM

static __device__ __forceinline__ void mma16816(float* c, uint32_t a0, uint32_t a1,
                                                uint32_t a2, uint32_t a3,
                                                uint32_t b0, uint32_t b1) {
    asm volatile(
        "mma.sync.aligned.m16n8k16.row.col.f32.f16.f16.f32 "
        "{%0,%1,%2,%3}, {%4,%5,%6,%7}, {%8,%9}, {%0,%1,%2,%3};"
        : "+f"(c[0]), "+f"(c[1]), "+f"(c[2]), "+f"(c[3])
        : "r"(a0), "r"(a1), "r"(a2), "r"(a3), "r"(b0), "r"(b1));
}

static __device__ __forceinline__ void ldsm4(uint32_t& a0, uint32_t& a1,
                                             uint32_t& a2, uint32_t& a3, uint32_t addr) {
    asm volatile("ldmatrix.sync.aligned.m8n8.x4.shared.b16 {%0,%1,%2,%3}, [%4];"
                 : "=r"(a0), "=r"(a1), "=r"(a2), "=r"(a3) : "r"(addr));
}

static __device__ __forceinline__ void cp16(uint32_t daddr, const float* src, uint32_t sz) {
    asm volatile("cp.async.cg.shared.global [%0], [%1], 16, %2;"
                 :: "r"(daddr), "l"(src), "r"(sz) : "memory");
}
static __device__ __forceinline__ void cp4(uint32_t daddr, const float* src, uint32_t sz) {
    asm volatile("cp.async.ca.shared.global [%0], [%1], 4, %2;"
                 :: "r"(daddr), "l"(src), "r"(sz) : "memory");
}

static __device__ __forceinline__ uint32_t smem_u32(const void* p) {
    uint32_t a;
    asm("{ .reg .u64 t; cvta.to.shared.u64 t, %1; cvt.u32.u64 %0, t; }" : "=r"(a) : "l"(p));
    return a;
}

static __device__ __forceinline__ void issue_tile_cp(const float* __restrict__ xin,
                                                     uint32_t sraw, int tile,
                                                     int ci, int xb) {
    const int x0 = (tile & 15) * 32, y0 = ((tile >> 4) & 31) * 16, n = tile >> 9;
    const float* src = xin + (size_t)(n * 16 + ci) * HW * HW;
    const uint32_t dbase = sraw + (uint32_t)(ci * NSY * RAWROW) * 4;

    const int c8 = xb & 7, yh = xb >> 3;
    #pragma unroll
    for (int j = 0; j < 9; ++j) {
        const int yy = 2 * j + yh;
        const int gy = y0 + yy - 1;
        const bool okY = (unsigned)gy < HW;
        const float* s = src + (size_t)(okY ? gy : 0) * HW + x0 + 4 * c8;
        cp16(dbase + (uint32_t)(yy * RAWROW + 4 * c8) * 4, s, okY ? 16u : 0u);
    }
    #pragma unroll
    for (int s2 = 0; s2 < 3; ++s2) {
        const int slot = xb + 16 * s2;
        if (slot < 2 * NSY) {
            const int yy = slot >> 1, side = slot & 1;
            const int gy = y0 + yy - 1;
            const int gx = side ? (x0 + 32) : (x0 - 1);
            const bool ok = ((unsigned)gy < HW) && ((unsigned)gx < HW);
            const float* s = src + (size_t)(ok ? gy : 0) * HW + (ok ? gx : 0);
            cp4(dbase + (uint32_t)(yy * RAWROW + 32 + side) * 4, s, ok ? 4u : 0u);
        }
    }
    asm volatile("cp.async.commit_group;" ::: "memory");
}

__global__ __launch_bounds__(256, 3)
void conv_mma_pipe(const float* __restrict__ xin,
                   const float* __restrict__ wgt,
                   float* __restrict__ out)
{
    extern __shared__ __align__(16) char smem[];
    float*  raw = (float*)(smem + RAW_OFF);
    __half* ns  = (__half*)(smem + NS_OFF);
    __half* Bs  = (__half*)(smem + BS_OFF);
    const uint32_t sraw = smem_u32(smem) + RAW_OFF;
    const uint32_t nsu  = smem_u32(smem) + NS_OFF;

    const int t    = threadIdx.x;
    const int lane = t & 31;
    const int wrp  = t >> 5;
    const int ci   = t >> 4;
    const int xb   = t & 15;

    #pragma unroll
    for (int r = 0; r < 9; ++r) {
        int idx = t + r * 256;
        int kh  = idx / 768;
        int rem = idx - kh * 768;
        int co  = rem / 48;
        int k   = rem - co * 48;
        Bs[idx] = __float2half_rn(wgt[co * 144 + (k & 15) * 9 + kh * 3 + (k >> 4)]);
    }

    const int g  = lane >> 2;
    const int cq = (lane & 3) * 2;
    const uint32_t fb = nsu + (uint32_t)(((lane & 15) * CPAD + (lane >> 4) * 8) * 2);

    const float* cvt_r0 = raw + (2 * wrp) * (NSY * RAWROW);
    const float* cvt_r1 = cvt_r0 + NSY * RAWROW;
    const int scolA = (lane == 0) ? 32 : (lane - 1);
    const int xxB   = 32 + lane;
    const int scolB = (xxB == 33) ? 33 : (xxB - 1);

    issue_tile_cp(xin, sraw, blockIdx.x, ci, xb);

    for (int tile = blockIdx.x; tile < NTILES; tile += GRID) {
        const int x0 = (tile & 15) * 32, y0 = ((tile >> 4) & 31) * 16, n = tile >> 9;

        asm volatile("cp.async.wait_group 0;" ::: "memory");
        __syncthreads();

        // ---- cvt raw fp32 -> ns fp16 ----
        #pragma unroll 3
        for (int yy = 0; yy < NSY; ++yy) {
            const int ro = yy * RAWROW;
            __half2 h = __floats2half2_rn(cvt_r0[ro + scolA], cvt_r1[ro + scolA]);
            *(__half2*)&ns[(yy * NSX + lane) * CPAD + 2 * wrp] = h;
            if (lane < 2) {
                __half2 h2 = __floats2half2_rn(cvt_r0[ro + scolB], cvt_r1[ro + scolB]);
                *(__half2*)&ns[(yy * NSX + xxB) * CPAD + 2 * wrp] = h2;
            }
        }
        __syncthreads();

        if (tile + GRID < NTILES)
            issue_tile_cp(xin, sraw, tile + GRID, ci, xb);

        // ---- compute ----
        float acc[4][2][4];
        #pragma unroll
        for (int i = 0; i < 4; ++i)
            #pragma unroll
            for (int nn = 0; nn < 2; ++nn)
                #pragma unroll
                for (int j = 0; j < 4; ++j) acc[i][nn][j] = 0.0f;

        #pragma unroll
        for (int dy = 0; dy < 3; ++dy) {
            uint32_t bf[3][2][2];
            #pragma unroll
            for (int kw = 0; kw < 3; ++kw)
                #pragma unroll
                for (int nn = 0; nn < 2; ++nn) {
                    const __half* bp = &Bs[(dy * 16 + nn * 8 + g) * 48 + kw * 16 + cq];
                    bf[kw][nn][0] = *(const uint32_t*)bp;
                    bf[kw][nn][1] = *(const uint32_t*)(bp + 8);
                }
            #pragma unroll
            for (int i = 0; i < 4; ++i) {
                const int m    = wrp * 4 + i;
                const int yloc = m >> 1;
                const int xh   = m & 1;
                const int yy   = yloc + dy;
                #pragma unroll
                for (int kw = 0; kw < 3; ++kw) {
                    uint32_t a0, a1, a2, a3;
                    ldsm4(a0, a1, a2, a3,
                          fb + (uint32_t)((yy * NSX + xh * 16 + kw) * (CPAD * 2)));
                    mma16816(acc[i][0], a0, a1, a2, a3, bf[kw][0][0], bf[kw][0][1]);
                    mma16816(acc[i][1], a0, a1, a2, a3, bf[kw][1][0], bf[kw][1][1]);
                }
            }
        }

        // ---- transposed epilogue: 2 rounds of 8 c_out through smem (ns as T) ----
        __syncthreads();                    // all LDSM of ns done; safe to reuse as T
        float* T = (float*)ns;
        #pragma unroll
        for (int rr = 0; rr < 2; ++rr) {
            #pragma unroll
            for (int i = 0; i < 4; ++i) {
                const int m    = wrp * 4 + i;
                const int yloc = m >> 1;
                const int xb2  = (m & 1) * 16 + g;
                float* tp = T + yloc * 32 + xb2;
                tp[cq * TCO]           = acc[i][rr][0];
                tp[(cq + 1) * TCO]     = acc[i][rr][1];
                tp[cq * TCO + 8]       = acc[i][rr][2];
                tp[(cq + 1) * TCO + 8] = acc[i][rr][3];
            }
            __syncthreads();
            // warp wrp handles co8 = wrp; 16 y rows x 32 x, STG.128 coalesced
            {
                const float* Tr = T + wrp * TCO;
                float* og = out + ((size_t)(n * 16 + rr * 8 + wrp) * HW + y0) * HW + x0;
                const int yq = lane >> 3, f4 = lane & 7;
                #pragma unroll
                for (int y4 = 0; y4 < 4; ++y4) {
                    const int y = y4 * 4 + yq;
                    float4 v = *(const float4*)&Tr[y * 32 + f4 * 4];
                    *(float4*)&og[(size_t)y * HW + f4 * 4] = v;
                }
            }
            if (rr == 0) __syncthreads();   // T reuse for round 1
        }
    }
}

extern "C" void kernel_launch(void* const* d_in, const int* in_sizes, int n_in,
                              void* d_out, int out_size) {
    const float* x = (const float*)d_in[0];   // [8,16,512,512]
    const float* w = (const float*)d_in[1];   // [16,144]
    float* out = (float*)d_out;

    static int attr_done = 0;
    if (!attr_done) {
        cudaFuncSetAttribute(conv_mma_pipe,
                             cudaFuncAttributeMaxDynamicSharedMemorySize, SM_TOTAL);
        attr_done = 1;
    }
    conv_mma_pipe<<<GRID, 256, SM_TOTAL>>>(x, w, out);
}

// round 8
// speedup vs baseline: 1.0252x; 1.0252x over previous
#include <cuda_runtime.h>
#include <cuda_fp16.h>
#include <cstdint>

// Conv2D 3x3 s1 p1: x[8,16,512,512] fp32 * w[16,144] -> out[8,16,512,512]
// Implicit GEMM on mma.sync.m16n8k16 (f16, f32 acc), persistent CTAs.
// R8: half-size raw staging (9 rows, 2 cp.async groups/tile) -> 54.7KB smem
// -> 4 CTAs/SM; A-frag register caching (36->24 LDSM/warp/tile); B-frags as
// u64 lanes (LDS.64). CTA tile: 32(x) x 16(y), all 16 co, 8 warps.

#define HW      512
#define NSX     34
#define NSY     18
#define CPAD    24       // ci stride (halves): 48B rows, LDSM conflict-free
#define RAWROW  36       // raw row: [0..31]=interior, [32]=x0-1, [33]=x0+32
#define RAWROWS 9        // half-tile staging depth
#define NTILES  4096
#define GRID    608      // 4 CTAs/SM x 152 SMs
#define TCO     516      // transpose co-stride (floats), == 4 mod 32

#define RAW_OFF 0                          // 16*9*36*4 = 20736 B
#define NS_OFF  20736                      // 18*34*24*2 = 29376 B (T needs 16512)
#define BS_OFF  (20736 + 29376)            // 50112; Bs2: 18*32*8 = 4608 B
#define SM_TOTAL (50112 + 4608)            // 54720 B -> 4 CTAs/SM

static __device__ __forceinline__ void mma16816(float* c, uint32_t a0, uint32_t a1,
                                                uint32_t a2, uint32_t a3,
                                                uint32_t b0, uint32_t b1) {
    asm volatile(
        "mma.sync.aligned.m16n8k16.row.col.f32.f16.f16.f32 "
        "{%0,%1,%2,%3}, {%4,%5,%6,%7}, {%8,%9}, {%0,%1,%2,%3};"
        : "+f"(c[0]), "+f"(c[1]), "+f"(c[2]), "+f"(c[3])
        : "r"(a0), "r"(a1), "r"(a2), "r"(a3), "r"(b0), "r"(b1));
}

static __device__ __forceinline__ void ldsm4(uint32_t& a0, uint32_t& a1,
                                             uint32_t& a2, uint32_t& a3, uint32_t addr) {
    asm volatile("ldmatrix.sync.aligned.m8n8.x4.shared.b16 {%0,%1,%2,%3}, [%4];"
                 : "=r"(a0), "=r"(a1), "=r"(a2), "=r"(a3) : "r"(addr));
}

static __device__ __forceinline__ void cp16(uint32_t daddr, const float* src, uint32_t sz) {
    asm volatile("cp.async.cg.shared.global [%0], [%1], 16, %2;"
                 :: "r"(daddr), "l"(src), "r"(sz) : "memory");
}
static __device__ __forceinline__ void cp4(uint32_t daddr, const float* src, uint32_t sz) {
    asm volatile("cp.async.ca.shared.global [%0], [%1], 4, %2;"
                 :: "r"(daddr), "l"(src), "r"(sz) : "memory");
}

static __device__ __forceinline__ uint32_t smem_u32(const void* p) {
    uint32_t a;
    asm("{ .reg .u64 t; cvta.to.shared.u64 t, %1; cvt.u32.u64 %0, t; }" : "=r"(a) : "l"(p));
    return a;
}

// Issue cp.async for 9 rows [lo, lo+9) of a tile's halo window; one commit group.
static __device__ __forceinline__ void issue_half(const float* __restrict__ xin,
                                                  uint32_t sraw, int tile, int lo,
                                                  int ci, int xb) {
    const int x0 = (tile & 15) * 32, y0 = ((tile >> 4) & 31) * 16, n = tile >> 9;
    const float* src = xin + (size_t)(n * 16 + ci) * HW * HW;
    const uint32_t dbase = sraw + (uint32_t)(ci * RAWROWS * RAWROW) * 4;
    const int c8 = xb & 7, yh = xb >> 3;

    #pragma unroll
    for (int j = 0; j < 5; ++j) {
        const int r = 2 * j + yh;
        if (r < RAWROWS) {
            const int gy = y0 + lo + r - 1;
            const bool okY = (unsigned)gy < HW;
            const float* s = src + (size_t)(okY ? gy : 0) * HW + x0 + 4 * c8;
            cp16(dbase + (uint32_t)(r * RAWROW + 4 * c8) * 4, s, okY ? 16u : 0u);
        }
    }
    #pragma unroll
    for (int s2 = 0; s2 < 2; ++s2) {
        const int slot = xb + 16 * s2;          // 18 halo slots per half
        if (slot < 2 * RAWROWS) {
            const int r = slot >> 1, side = slot & 1;
            const int gy = y0 + lo + r - 1;
            const int gx = side ? (x0 + 32) : (x0 - 1);
            const bool ok = ((unsigned)gy < HW) && ((unsigned)gx < HW);
            const float* s = src + (size_t)(ok ? gy : 0) * HW + (ok ? gx : 0);
            cp4(dbase + (uint32_t)(r * RAWROW + 32 + side) * 4, s, ok ? 4u : 0u);
        }
    }
    asm volatile("cp.async.commit_group;" ::: "memory");
}

__global__ __launch_bounds__(256, 4)
void conv_mma_pipe(const float* __restrict__ xin,
                   const float* __restrict__ wgt,
                   float* __restrict__ out)
{
    extern __shared__ __align__(16) char smem[];
    float*  raw = (float*)(smem + RAW_OFF);
    __half* ns  = (__half*)(smem + NS_OFF);
    uint2*  Bs2 = (uint2*)(smem + BS_OFF);
    const uint32_t sraw = smem_u32(smem) + RAW_OFF;
    const uint32_t nsu  = smem_u32(smem) + NS_OFF;

    const int t    = threadIdx.x;
    const int lane = t & 31;
    const int wrp  = t >> 5;
    const int ci   = t >> 4;     // cp.async mapping
    const int xb   = t & 15;

    // ---- stage weights once: Bs2[slot=(dy*3+kw)*2+nn][lane] = {b0,b1} ----
    #pragma unroll
    for (int e = t; e < 576; e += 256) {
        const int slot = e >> 5, l2 = e & 31;
        const int g2 = l2 >> 2, cq2 = (l2 & 3) * 2;
        const int nn = slot & 1, kwk = (slot >> 1) % 3, dy = slot / 6;
        const float* wb = wgt + (nn * 8 + g2) * 144 + dy * 3 + kwk;
        __half2 w0 = __floats2half2_rn(wb[cq2 * 9],       wb[(cq2 + 1) * 9]);
        __half2 w1 = __floats2half2_rn(wb[(cq2 + 8) * 9], wb[(cq2 + 9) * 9]);
        uint2 v;
        v.x = *(const uint32_t*)&w0;
        v.y = *(const uint32_t*)&w1;
        Bs2[e] = v;
    }

    const int g  = lane >> 2;
    const int cq = (lane & 3) * 2;
    const uint32_t fb = nsu + (uint32_t)(((lane & 15) * CPAD + (lane >> 4) * 8) * 2);

    // cvt mapping: ci pair = wrp, lane = ns x-column
    const float* cr0 = raw + (2 * wrp) * (RAWROWS * RAWROW);
    const float* cr1 = cr0 + RAWROWS * RAWROW;
    const int scolA = (lane == 0) ? 32 : (lane - 1);
    const int xxB   = 32 + lane;
    const int scolB = (xxB == 33) ? 33 : (xxB - 1);

    issue_half(xin, sraw, blockIdx.x, 0, ci, xb);

    for (int tile = blockIdx.x; tile < NTILES; tile += GRID) {
        const int x0 = (tile & 15) * 32, y0 = ((tile >> 4) & 31) * 16, n = tile >> 9;

        // ---- half A: rows 0-8 ----
        asm volatile("cp.async.wait_group 0;" ::: "memory");
        __syncthreads();
        #pragma unroll 3
        for (int r = 0; r < RAWROWS; ++r) {
            const int ro = r * RAWROW;
            __half2 h = __floats2half2_rn(cr0[ro + scolA], cr1[ro + scolA]);
            *(__half2*)&ns[(r * NSX + lane) * CPAD + 2 * wrp] = h;
            if (lane < 2) {
                __half2 h2 = __floats2half2_rn(cr0[ro + scolB], cr1[ro + scolB]);
                *(__half2*)&ns[(r * NSX + xxB) * CPAD + 2 * wrp] = h2;
            }
        }
        __syncthreads();                       // raw consumed
        issue_half(xin, sraw, tile, RAWROWS, ci, xb);

        // ---- half B: rows 9-17 ----
        asm volatile("cp.async.wait_group 0;" ::: "memory");
        __syncthreads();
        #pragma unroll 3
        for (int r = 0; r < RAWROWS; ++r) {
            const int ro = r * RAWROW;
            const int yy = RAWROWS + r;
            __half2 h = __floats2half2_rn(cr0[ro + scolA], cr1[ro + scolA]);
            *(__half2*)&ns[(yy * NSX + lane) * CPAD + 2 * wrp] = h;
            if (lane < 2) {
                __half2 h2 = __floats2half2_rn(cr0[ro + scolB], cr1[ro + scolB]);
                *(__half2*)&ns[(yy * NSX + xxB) * CPAD + 2 * wrp] = h2;
            }
        }
        __syncthreads();                       // raw consumed; ns complete
        if (tile + GRID < NTILES)
            issue_half(xin, sraw, tile + GRID, 0, ci, xb);   // overlaps compute

        // ---- compute: kw -> (B frags) -> xh -> 4 cached A frags -> 12 MMA ----
        float acc[4][2][4];
        #pragma unroll
        for (int i = 0; i < 4; ++i)
            #pragma unroll
            for (int nn = 0; nn < 2; ++nn)
                #pragma unroll
                for (int j = 0; j < 4; ++j) acc[i][nn][j] = 0.0f;

        #pragma unroll
        for (int kw = 0; kw < 3; ++kw) {
            uint32_t bf[3][2][2];
            #pragma unroll
            for (int dy = 0; dy < 3; ++dy)
                #pragma unroll
                for (int nn = 0; nn < 2; ++nn) {
                    uint2 v = Bs2[((dy * 3 + kw) * 2 + nn) * 32 + lane];
                    bf[dy][nn][0] = v.x;
                    bf[dy][nn][1] = v.y;
                }
            #pragma unroll
            for (int xh = 0; xh < 2; ++xh) {
                uint32_t F[4][4];
                #pragma unroll
                for (int q = 0; q < 4; ++q)
                    ldsm4(F[q][0], F[q][1], F[q][2], F[q][3],
                          fb + (uint32_t)(((2 * wrp + q) * NSX + xh * 16 + kw) * (CPAD * 2)));
                #pragma unroll
                for (int yl = 0; yl < 2; ++yl)
                    #pragma unroll
                    for (int dy = 0; dy < 3; ++dy) {
                        const int q = yl + dy;
                        const int i = yl * 2 + xh;
                        mma16816(acc[i][0], F[q][0], F[q][1], F[q][2], F[q][3],
                                 bf[dy][0][0], bf[dy][0][1]);
                        mma16816(acc[i][1], F[q][0], F[q][1], F[q][2], F[q][3],
                                 bf[dy][1][0], bf[dy][1][1]);
                    }
            }
        }

        // ---- transposed epilogue: 2 rounds of 8 c_out through smem (ns as T) ----
        __syncthreads();                    // LDSM done; ns reusable as T
        float* T = (float*)ns;
        #pragma unroll
        for (int rr = 0; rr < 2; ++rr) {
            #pragma unroll
            for (int i = 0; i < 4; ++i) {
                const int m    = wrp * 4 + i;
                const int yloc = m >> 1;
                const int xb2  = (m & 1) * 16 + g;
                float* tp = T + yloc * 32 + xb2;
                tp[cq * TCO]           = acc[i][rr][0];
                tp[(cq + 1) * TCO]     = acc[i][rr][1];
                tp[cq * TCO + 8]       = acc[i][rr][2];
                tp[(cq + 1) * TCO + 8] = acc[i][rr][3];
            }
            __syncthreads();
            {
                const float* Tr = T + wrp * TCO;
                float* og = out + ((size_t)(n * 16 + rr * 8 + wrp) * HW + y0) * HW + x0;
                const int yq = lane >> 3, f4 = lane & 7;
                #pragma unroll
                for (int y4 = 0; y4 < 4; ++y4) {
                    const int y = y4 * 4 + yq;
                    float4 v = *(const float4*)&Tr[y * 32 + f4 * 4];
                    *(float4*)&og[(size_t)y * HW + f4 * 4] = v;
                }
            }
            if (rr == 0) __syncthreads();
        }
    }
}

extern "C" void kernel_launch(void* const* d_in, const int* in_sizes, int n_in,
                              void* d_out, int out_size) {
    const float* x = (const float*)d_in[0];   // [8,16,512,512]
    const float* w = (const float*)d_in[1];   // [16,144]
    float* out = (float*)d_out;

    static int attr_done = 0;
    if (!attr_done) {
        cudaFuncSetAttribute(conv_mma_pipe,
                             cudaFuncAttributeMaxDynamicSharedMemorySize, SM_TOTAL);
        attr_done = 1;
    }
    conv_mma_pipe<<<GRID, 256, SM_TOTAL>>>(x, w, out);
}

// round 9
// speedup vs baseline: 1.0371x; 1.0115x over previous
#include <cuda_runtime.h>
#include <cuda_fp16.h>
#include <cstdint>

// Conv2D 3x3 s1 p1: x[8,16,512,512] fp32 * w[16,144] -> out[8,16,512,512]
// Implicit GEMM on mma.sync.m16n8k16 (f16, f32 acc), persistent CTAs.
// R9: minimal-phase pipeline — full-tile raw prefetch (wait fully hidden),
// ONE cvt phase, TWO barriers/tile, direct-store epilogue (no smem T),
// R8 compute core (u64 B-frags, A-frag register caching).
// CTA tile: 32(x) x 16(y), all 16 co, 8 warps. 3 CTAs/SM.

#define HW      512
#define NSX     34
#define NSY     18
#define CPAD    24       // ci stride (halves): 48B rows, LDSM conflict-free
#define RAWROW  36       // raw row: [0..31]=interior, [32]=x0-1, [33]=x0+32
#define NTILES  4096
#define GRID    456      // 3 CTAs/SM x 152 SMs

#define RAW_OFF 0                          // 16*18*36*4 = 41472 B
#define NS_OFF  41472                      // 18*34*24*2 = 29376 B
#define BS_OFF  (41472 + 29376)            // 70848; Bs2: 18*32*8 = 4608 B
#define SM_TOTAL (70848 + 4608)            // 75456 B -> 3 CTAs/SM

static __device__ __forceinline__ void mma16816(float* c, uint32_t a0, uint32_t a1,
                                                uint32_t a2, uint32_t a3,
                                                uint32_t b0, uint32_t b1) {
    asm volatile(
        "mma.sync.aligned.m16n8k16.row.col.f32.f16.f16.f32 "
        "{%0,%1,%2,%3}, {%4,%5,%6,%7}, {%8,%9}, {%0,%1,%2,%3};"
        : "+f"(c[0]), "+f"(c[1]), "+f"(c[2]), "+f"(c[3])
        : "r"(a0), "r"(a1), "r"(a2), "r"(a3), "r"(b0), "r"(b1));
}

static __device__ __forceinline__ void ldsm4(uint32_t& a0, uint32_t& a1,
                                             uint32_t& a2, uint32_t& a3, uint32_t addr) {
    asm volatile("ldmatrix.sync.aligned.m8n8.x4.shared.b16 {%0,%1,%2,%3}, [%4];"
                 : "=r"(a0), "=r"(a1), "=r"(a2), "=r"(a3) : "r"(addr));
}

static __device__ __forceinline__ void cp16(uint32_t daddr, const float* src, uint32_t sz) {
    asm volatile("cp.async.cg.shared.global [%0], [%1], 16, %2;"
                 :: "r"(daddr), "l"(src), "r"(sz) : "memory");
}
static __device__ __forceinline__ void cp4(uint32_t daddr, const float* src, uint32_t sz) {
    asm volatile("cp.async.ca.shared.global [%0], [%1], 4, %2;"
                 :: "r"(daddr), "l"(src), "r"(sz) : "memory");
}

static __device__ __forceinline__ uint32_t smem_u32(const void* p) {
    uint32_t a;
    asm("{ .reg .u64 t; cvta.to.shared.u64 t, %1; cvt.u32.u64 %0, t; }" : "=r"(a) : "l"(p));
    return a;
}

// Issue cp.async for a full tile's 18-row halo window; one commit group.
static __device__ __forceinline__ void issue_tile_cp(const float* __restrict__ xin,
                                                     uint32_t sraw, int tile,
                                                     int ci, int xb) {
    const int x0 = (tile & 15) * 32, y0 = ((tile >> 4) & 31) * 16, n = tile >> 9;
    const float* src = xin + (size_t)(n * 16 + ci) * HW * HW;
    const uint32_t dbase = sraw + (uint32_t)(ci * NSY * RAWROW) * 4;

    const int c8 = xb & 7, yh = xb >> 3;
    #pragma unroll
    for (int j = 0; j < 9; ++j) {
        const int yy = 2 * j + yh;
        const int gy = y0 + yy - 1;
        const bool okY = (unsigned)gy < HW;
        const float* s = src + (size_t)(okY ? gy : 0) * HW + x0 + 4 * c8;
        cp16(dbase + (uint32_t)(yy * RAWROW + 4 * c8) * 4, s, okY ? 16u : 0u);
    }
    #pragma unroll
    for (int s2 = 0; s2 < 3; ++s2) {
        const int slot = xb + 16 * s2;
        if (slot < 2 * NSY) {
            const int yy = slot >> 1, side = slot & 1;
            const int gy = y0 + yy - 1;
            const int gx = side ? (x0 + 32) : (x0 - 1);
            const bool ok = ((unsigned)gy < HW) && ((unsigned)gx < HW);
            const float* s = src + (size_t)(ok ? gy : 0) * HW + (ok ? gx : 0);
            cp4(dbase + (uint32_t)(yy * RAWROW + 32 + side) * 4, s, ok ? 4u : 0u);
        }
    }
    asm volatile("cp.async.commit_group;" ::: "memory");
}

__global__ __launch_bounds__(256, 3)
void conv_mma_pipe(const float* __restrict__ xin,
                   const float* __restrict__ wgt,
                   float* __restrict__ out)
{
    extern __shared__ __align__(16) char smem[];
    float*  raw = (float*)(smem + RAW_OFF);
    __half* ns  = (__half*)(smem + NS_OFF);
    uint2*  Bs2 = (uint2*)(smem + BS_OFF);
    const uint32_t sraw = smem_u32(smem) + RAW_OFF;
    const uint32_t nsu  = smem_u32(smem) + NS_OFF;

    const int t    = threadIdx.x;
    const int lane = t & 31;
    const int wrp  = t >> 5;
    const int ci   = t >> 4;     // cp.async mapping
    const int xb   = t & 15;

    // ---- stage weights once: Bs2[slot=(dy*3+kw)*2+nn][lane] = {b0,b1} ----
    #pragma unroll
    for (int e = t; e < 576; e += 256) {
        const int slot = e >> 5, l2 = e & 31;
        const int g2 = l2 >> 2, cq2 = (l2 & 3) * 2;
        const int nn = slot & 1, kwk = (slot >> 1) % 3, dy = slot / 6;
        const float* wb = wgt + (nn * 8 + g2) * 144 + dy * 3 + kwk;
        __half2 w0 = __floats2half2_rn(wb[cq2 * 9],       wb[(cq2 + 1) * 9]);
        __half2 w1 = __floats2half2_rn(wb[(cq2 + 8) * 9], wb[(cq2 + 9) * 9]);
        uint2 v;
        v.x = *(const uint32_t*)&w0;
        v.y = *(const uint32_t*)&w1;
        Bs2[e] = v;
    }

    const int g  = lane >> 2;
    const int cq = (lane & 3) * 2;
    const uint32_t fb = nsu + (uint32_t)(((lane & 15) * CPAD + (lane >> 4) * 8) * 2);

    // cvt mapping: ci pair = wrp, lane = ns x-column
    const float* cr0 = raw + (2 * wrp) * (NSY * RAWROW);
    const float* cr1 = cr0 + NSY * RAWROW;
    const int scolA = (lane == 0) ? 32 : (lane - 1);
    const int xxB   = 32 + lane;
    const int scolB = (xxB == 33) ? 33 : (xxB - 1);

    issue_tile_cp(xin, sraw, blockIdx.x, ci, xb);

    for (int tile = blockIdx.x; tile < NTILES; tile += GRID) {
        const int x0 = (tile & 15) * 32, y0 = ((tile >> 4) & 31) * 16, n = tile >> 9;

        // ---- wait (group issued one compute-phase ago -> hidden) ----
        asm volatile("cp.async.wait_group 0;" ::: "memory");
        __syncthreads();                            // bar1: raw visible to all

        // ---- single cvt phase: raw fp32 -> ns fp16 ----
        #pragma unroll 3
        for (int yy = 0; yy < NSY; ++yy) {
            const int ro = yy * RAWROW;
            __half2 h = __floats2half2_rn(cr0[ro + scolA], cr1[ro + scolA]);
            *(__half2*)&ns[(yy * NSX + lane) * CPAD + 2 * wrp] = h;
            if (lane < 2) {
                __half2 h2 = __floats2half2_rn(cr0[ro + scolB], cr1[ro + scolB]);
                *(__half2*)&ns[(yy * NSX + xxB) * CPAD + 2 * wrp] = h2;
            }
        }
        __syncthreads();                            // bar2: ns ready, raw free

        // ---- prefetch next tile (hidden under compute + epilogue) ----
        if (tile + GRID < NTILES)
            issue_tile_cp(xin, sraw, tile + GRID, ci, xb);

        // ---- compute: kw -> B frags -> xh -> 4 cached A frags -> 12 MMA ----
        float acc[4][2][4];
        #pragma unroll
        for (int i = 0; i < 4; ++i)
            #pragma unroll
            for (int nn = 0; nn < 2; ++nn)
                #pragma unroll
                for (int j = 0; j < 4; ++j) acc[i][nn][j] = 0.0f;

        #pragma unroll
        for (int kw = 0; kw < 3; ++kw) {
            uint32_t bf[3][2][2];
            #pragma unroll
            for (int dy = 0; dy < 3; ++dy)
                #pragma unroll
                for (int nn = 0; nn < 2; ++nn) {
                    uint2 v = Bs2[((dy * 3 + kw) * 2 + nn) * 32 + lane];
                    bf[dy][nn][0] = v.x;
                    bf[dy][nn][1] = v.y;
                }
            #pragma unroll
            for (int xh = 0; xh < 2; ++xh) {
                uint32_t F[4][4];
                #pragma unroll
                for (int q = 0; q < 4; ++q)
                    ldsm4(F[q][0], F[q][1], F[q][2], F[q][3],
                          fb + (uint32_t)(((2 * wrp + q) * NSX + xh * 16 + kw) * (CPAD * 2)));
                #pragma unroll
                for (int yl = 0; yl < 2; ++yl)
                    #pragma unroll
                    for (int dy = 0; dy < 3; ++dy) {
                        const int q = yl + dy;
                        const int i = yl * 2 + xh;
                        mma16816(acc[i][0], F[q][0], F[q][1], F[q][2], F[q][3],
                                 bf[dy][0][0], bf[dy][0][1]);
                        mma16816(acc[i][1], F[q][0], F[q][1], F[q][2], F[q][3],
                                 bf[dy][1][0], bf[dy][1][1]);
                    }
            }
        }

        // ---- direct-store epilogue (no smem, no barriers) ----
        #pragma unroll
        for (int i = 0; i < 4; ++i) {
            const int yloc = wrp * 2 + (i >> 1);
            const int xh   = i & 1;
            const int y  = y0 + yloc;
            const int xg = x0 + xh * 16 + g;
            #pragma unroll
            for (int nn = 0; nn < 2; ++nn) {
                const int co = nn * 8 + cq;
                float* op = out + ((size_t)(n * 16 + co) * HW + y) * HW + xg;
                op[0]                   = acc[i][nn][0];
                op[(size_t)HW * HW]     = acc[i][nn][1];
                op[8]                   = acc[i][nn][2];
                op[(size_t)HW * HW + 8] = acc[i][nn][3];
            }
        }
    }
}

extern "C" void kernel_launch(void* const* d_in, const int* in_sizes, int n_in,
                              void* d_out, int out_size) {
    const float* x = (const float*)d_in[0];   // [8,16,512,512]
    const float* w = (const float*)d_in[1];   // [16,144]
    float* out = (float*)d_out;

    static int attr_done = 0;
    if (!attr_done) {
        cudaFuncSetAttribute(conv_mma_pipe,
                             cudaFuncAttributeMaxDynamicSharedMemorySize, SM_TOTAL);
        attr_done = 1;
    }
    conv_mma_pipe<<<GRID, 256, SM_TOTAL>>>(x, w, out);
}